// round 6
// baseline (speedup 1.0000x reference)
#include <cuda_runtime.h>
#include <cuda_bf16.h>
#include <math.h>
#include <stdint.h>

// ---------------- problem constants ----------------
#define BB   16
#define TT   4096
#define NR   (BB*TT)       // 65536 rows
#define TSD  64
#define DE   128
#define HH   256
#define LDF  512
#define LDH  256
#define OD   10
#define NBLKS 6
#define EPSV 1e-5f
#define NCH  16
#define CLEN 256

// ---------------- scratch ----------------
static __device__ __align__(256) float  g_yenc[(size_t)NR*DE];
static __device__ __align__(256) float  g_h   [(size_t)NR*DE];
static __device__ __align__(256) __nv_bfloat16 g_bu16[(size_t)NR*512];   // Bu bf16
static __device__ __align__(256) float2 g_state[(size_t)NR*HH];          // scan state fp32
static __device__ __align__(256) float  g_lru [(size_t)NR*DE];
static __device__ __align__(256) float  g_glu [(size_t)NR*LDH];
static __device__ float2 g_lam [NBLKS*HH];
static __device__ float  g_gamma[NBLKS*HH];
static __device__ float  g_bnpart[512*2*DE];
static __device__ float  g_bna[DE];
static __device__ float  g_bnb[DE];
static __device__ float2 g_carry[BB*NCH*HH];
static __device__ float2 g_inc  [BB*NCH*HH];

// split bf16 weights, [blk][n][k]
static __device__ __align__(256) __nv_bfloat16 g_WBh[(size_t)NBLKS*512*128];
static __device__ __align__(256) __nv_bfloat16 g_WBl[(size_t)NBLKS*512*128];
static __device__ __align__(256) __nv_bfloat16 g_WCh[(size_t)NBLKS*128*512];
static __device__ __align__(256) __nv_bfloat16 g_WCl[(size_t)NBLKS*128*512];
static __device__ __align__(256) __nv_bfloat16 g_W1h[(size_t)NBLKS*512*128];
static __device__ __align__(256) __nv_bfloat16 g_W1l[(size_t)NBLKS*512*128];
static __device__ __align__(256) __nv_bfloat16 g_W2h[(size_t)NBLKS*128*256];
static __device__ __align__(256) __nv_bfloat16 g_W2l[(size_t)NBLKS*128*256];
static __device__ __align__(256) __nv_bfloat16 g_WEh[128*64];
static __device__ __align__(256) __nv_bfloat16 g_WEl[128*64];

// ---------------- helpers ----------------
__device__ __forceinline__ uint32_t smem_u32(const void* p) {
    uint32_t a;
    asm("{ .reg .u64 t; cvta.to.shared.u64 t, %1; cvt.u32.u64 %0, t; }" : "=r"(a) : "l"(p));
    return a;
}
__device__ __forceinline__ void cp16(uint32_t dst, const void* src) {
    asm volatile("cp.async.cg.shared.global [%0], [%1], 16;" :: "r"(dst), "l"(src));
}
#define CP_COMMIT() asm volatile("cp.async.commit_group;" ::: "memory")
#define CP_WAIT0()  asm volatile("cp.async.wait_group 0;" ::: "memory")

#define MMA_BF16(d, a0, a1, a2, a3, b0, b1) \
    asm volatile("mma.sync.aligned.m16n8k16.row.col.f32.bf16.bf16.f32 " \
        "{%0,%1,%2,%3}, {%4,%5,%6,%7}, {%8,%9}, {%0,%1,%2,%3};" \
        : "+f"((d)[0]), "+f"((d)[1]), "+f"((d)[2]), "+f"((d)[3]) \
        : "r"(a0), "r"(a1), "r"(a2), "r"(a3), "r"(b0), "r"(b1))

// ---------------- prep ----------------
__global__ void prep_lam_kernel(const float* __restrict__ nu_log,
                                const float* __restrict__ theta_log) {
    int blk = blockIdx.x;
    int h   = threadIdx.x;
    float nu = nu_log[blk*HH + h];
    float th = theta_log[blk*HH + h];
    float r  = expf(-expf(nu));
    float ang = expf(th);
    float sn, cs;
    sincosf(ang, &sn, &cs);
    float2 lam; lam.x = r*cs; lam.y = r*sn;
    g_lam[blk*HH + h]   = lam;
    g_gamma[blk*HH + h] = sqrtf(fmaxf(1.f - r*r, 1e-8f));
}
__device__ __forceinline__ void split_store(float v, __nv_bfloat16* hi, __nv_bfloat16* lo, size_t i) {
    __nv_bfloat16 h = __float2bfloat16(v);
    hi[i] = h;
    lo[i] = __float2bfloat16(v - __bfloat162float(h));
}
__global__ void prep_WB_kernel(const float* __restrict__ Bre, const float* __restrict__ Bim) {
    int idx = blockIdx.x*256 + threadIdx.x;
    if (idx >= NBLKS*512*DE) return;
    int k = idx & 127;
    int n = (idx >> 7) & 511;
    int blk = idx >> 16;
    int h = n >> 1;
    float g = g_gamma[blk*HH + h];
    float v = ((n & 1) ? Bim : Bre)[((size_t)blk*HH + h)*DE + k] * g;
    split_store(v, g_WBh, g_WBl, idx);
}
__global__ void prep_WC_kernel(const float* __restrict__ Cre, const float* __restrict__ Cim) {
    int idx = blockIdx.x*256 + threadIdx.x;
    if (idx >= NBLKS*DE*512) return;
    int k = idx & 511;
    int n = (idx >> 9) & 127;
    int blk = idx >> 16;
    int h = k >> 1;
    float v = (k & 1) ? -Cim[((size_t)blk*DE + n)*HH + h] : Cre[((size_t)blk*DE + n)*HH + h];
    split_store(v, g_WCh, g_WCl, idx);
}
__global__ void prep_W1_kernel(const float* __restrict__ W1) {
    int idx = blockIdx.x*256 + threadIdx.x;
    if (idx >= NBLKS*512*DE) return;
    int k = idx & 127;
    int n = (idx >> 7) & 511;
    int blk = idx >> 16;
    float v = W1[((size_t)blk*DE + k)*LDF + n];
    split_store(v, g_W1h, g_W1l, idx);
}
__global__ void prep_W2_kernel(const float* __restrict__ W2) {
    int idx = blockIdx.x*256 + threadIdx.x;
    if (idx >= NBLKS*DE*256) return;
    int k = idx & 255;
    int n = (idx >> 8) & 127;
    int blk = idx >> 15;
    float v = W2[((size_t)blk*LDH + k)*DE + n];
    split_store(v, g_W2h, g_W2l, idx);
}
__global__ void prep_WE_kernel(const float* __restrict__ We) {
    int idx = blockIdx.x*256 + threadIdx.x;
    if (idx >= DE*TSD) return;
    int k = idx & 63;
    int n = idx >> 6;
    float v = We[(size_t)k*DE + n];
    split_store(v, g_WEh, g_WEl, idx);
}

// ---------------- batchnorm stage-2 ----------------
__global__ void bn_stats2_kernel(const float* __restrict__ scale,
                                 const float* __restrict__ bias) {
    int f = threadIdx.x;
    float s = 0.f, s2 = 0.f;
    for (int i = 0; i < 512; i++) {
        s  += g_bnpart[i*(2*DE) + f];
        s2 += g_bnpart[i*(2*DE) + DE + f];
    }
    float mean = s * (1.f/NR);
    float var  = s2 * (1.f/NR) - mean*mean;
    float a = scale[f] * rsqrtf(var + EPSV);
    g_bna[f] = a;
    g_bnb[f] = fmaf(-mean, a, bias[f]);
}

// ---------------- pipelined bf16x3 mma.sync GEMM, K-chunk 32, 2 CTA/SM ----------------
#define PITCH 40
#define UNITE (128*PITCH)
#define STAGEE (4*UNITE)
#define SMEM_BYTES (2*STAGEE*2)      // 81920

template<int KDIM, int OUTW, int MODE_A, int EPI, int DUAL, int OUT16, int STATS>
__global__ void __launch_bounds__(256, 2) gemm_mma(
    const float* __restrict__ A,
    const __nv_bfloat16* __restrict__ Bhi,
    const __nv_bfloat16* __restrict__ Blo,
    float* __restrict__ C,
    const float* __restrict__ bias,
    const float* __restrict__ aux,
    const float* __restrict__ dvec)
{
    constexpr int O_AH = 0, O_AL = UNITE, O_BH = 2*UNITE, O_BL = 3*UNITE;
    constexpr int NCHK = KDIM / 32;

    extern __shared__ __nv_bfloat16 sm[];
    const uint32_t smb = smem_u32(sm);
    const int tid  = threadIdx.x;
    const int wid  = tid >> 5;
    const int lane = tid & 31;
    const int wr   = wid & 3;
    const int wc2  = wid >> 2;
    const int g    = lane >> 2;
    const int t    = lane & 3;
    const int bm   = blockIdx.y << 7;
    const int bn   = DUAL ? (blockIdx.x << 6) : (blockIdx.x << 7);

    float accg[2][DUAL ? 4 : 8][4];
    float accs[DUAL ? 2 : 1][DUAL ? 4 : 1][4];
    #pragma unroll
    for (int rb = 0; rb < 2; rb++)
        #pragma unroll
        for (int nb = 0; nb < (DUAL ? 4 : 8); nb++)
            #pragma unroll
            for (int j = 0; j < 4; j++) {
                accg[rb][nb][j] = 0.f;
                if (DUAL) accs[rb][nb][j] = 0.f;
            }

    const int arow = tid >> 1;
    const int ahalf = (tid & 1) << 4;
    float4 areg[4];
    auto loadA = [&](int cc) {
        const float* p = A + (size_t)(bm + arow)*KDIM + cc*32 + ahalf;
        areg[0] = *(const float4*)(p + 0);
        areg[1] = *(const float4*)(p + 4);
        areg[2] = *(const float4*)(p + 8);
        areg[3] = *(const float4*)(p + 12);
    };
    auto storeA = [&](int cc, int so) {
        uint32_t hu[8], lu[8];
        #pragma unroll
        for (int q = 0; q < 4; q++) {
            float4 v = areg[q];
            if (MODE_A) {
                const float* aa = g_bna + cc*32 + ahalf + q*4;
                const float* ab = g_bnb + cc*32 + ahalf + q*4;
                v.x = fmaf(aa[0], v.x, ab[0]);
                v.y = fmaf(aa[1], v.y, ab[1]);
                v.z = fmaf(aa[2], v.z, ab[2]);
                v.w = fmaf(aa[3], v.w, ab[3]);
            }
            __nv_bfloat16 h0 = __float2bfloat16(v.x), h1 = __float2bfloat16(v.y);
            __nv_bfloat16 h2 = __float2bfloat16(v.z), h3 = __float2bfloat16(v.w);
            __nv_bfloat16 l0 = __float2bfloat16(v.x - __bfloat162float(h0));
            __nv_bfloat16 l1 = __float2bfloat16(v.y - __bfloat162float(h1));
            __nv_bfloat16 l2 = __float2bfloat16(v.z - __bfloat162float(h2));
            __nv_bfloat16 l3 = __float2bfloat16(v.w - __bfloat162float(h3));
            hu[q*2+0] = ((uint32_t)__bfloat16_as_ushort(h1) << 16) | __bfloat16_as_ushort(h0);
            hu[q*2+1] = ((uint32_t)__bfloat16_as_ushort(h3) << 16) | __bfloat16_as_ushort(h2);
            lu[q*2+0] = ((uint32_t)__bfloat16_as_ushort(l1) << 16) | __bfloat16_as_ushort(l0);
            lu[q*2+1] = ((uint32_t)__bfloat16_as_ushort(l3) << 16) | __bfloat16_as_ushort(l2);
        }
        int off = arow*PITCH + ahalf;
        *(uint4*)(sm + so + O_AH + off)     = make_uint4(hu[0], hu[1], hu[2], hu[3]);
        *(uint4*)(sm + so + O_AH + off + 8) = make_uint4(hu[4], hu[5], hu[6], hu[7]);
        *(uint4*)(sm + so + O_AL + off)     = make_uint4(lu[0], lu[1], lu[2], lu[3]);
        *(uint4*)(sm + so + O_AL + off + 8) = make_uint4(lu[4], lu[5], lu[6], lu[7]);
    };
    auto cpB = [&](int cc, int so) {
        #pragma unroll
        for (int i = 0; i < 4; i++) {
            int idx  = tid + 256*i;
            int part = idx >> 9;
            int rem  = idx & 511;
            int r    = rem >> 2;
            int q    = rem & 3;
            int rowg = DUAL ? (r < 64 ? bn + r : bn + 256 + (r - 64)) : (bn + r);
            const __nv_bfloat16* src = part ? Blo : Bhi;
            cp16(smb + (uint32_t)((so + (part ? O_BL : O_BH) + r*PITCH + q*8)*2),
                 src + (size_t)rowg*KDIM + cc*32 + q*8);
        }
    };

    // prologue: stage chunk 0
    loadA(0);
    cpB(0, 0);
    CP_COMMIT();
    storeA(0, 0);
    if (NCHK > 1) loadA(1);

    #pragma unroll 1
    for (int c = 0; c < NCHK; c++) {
        const int so = (c & 1)*STAGEE;
        // SAFE ordering: drain pending copies, barrier, THEN touch the other stage.
        CP_WAIT0();
        __syncthreads();
        if (c + 1 < NCHK) {
            const int nso = ((c+1) & 1)*STAGEE;
            cpB(c+1, nso);          // overlaps with compute(so) below
            CP_COMMIT();
            storeA(c+1, nso);
            if (c + 2 < NCHK) loadA(c+2);
        }

        #pragma unroll
        for (int kk = 0; kk < 2; kk++) {
            const int kb = kk*16 + 2*t;
            uint32_t ah[2][4], al[2][4];
            #pragma unroll
            for (int rb = 0; rb < 2; rb++) {
                int ao = so + (32*wr + 16*rb + g)*PITCH + kb;
                ah[rb][0] = *(const uint32_t*)(sm + O_AH + ao);
                ah[rb][1] = *(const uint32_t*)(sm + O_AH + ao + 8*PITCH);
                ah[rb][2] = *(const uint32_t*)(sm + O_AH + ao + 8);
                ah[rb][3] = *(const uint32_t*)(sm + O_AH + ao + 8*PITCH + 8);
                al[rb][0] = *(const uint32_t*)(sm + O_AL + ao);
                al[rb][1] = *(const uint32_t*)(sm + O_AL + ao + 8*PITCH);
                al[rb][2] = *(const uint32_t*)(sm + O_AL + ao + 8);
                al[rb][3] = *(const uint32_t*)(sm + O_AL + ao + 8*PITCH + 8);
            }
            if (!DUAL) {
                #pragma unroll
                for (int nb = 0; nb < 8; nb++) {
                    int bo = so + (64*wc2 + 8*nb + g)*PITCH + kb;
                    uint32_t b0 = *(const uint32_t*)(sm + O_BH + bo);
                    uint32_t b1 = *(const uint32_t*)(sm + O_BH + bo + 8);
                    uint32_t c0 = *(const uint32_t*)(sm + O_BL + bo);
                    uint32_t c1 = *(const uint32_t*)(sm + O_BL + bo + 8);
                    #pragma unroll
                    for (int rb = 0; rb < 2; rb++) {
                        MMA_BF16(accg[rb][nb], ah[rb][0], ah[rb][1], ah[rb][2], ah[rb][3], b0, b1);
                        MMA_BF16(accg[rb][nb], al[rb][0], al[rb][1], al[rb][2], al[rb][3], b0, b1);
                        MMA_BF16(accg[rb][nb], ah[rb][0], ah[rb][1], ah[rb][2], ah[rb][3], c0, c1);
                    }
                }
            } else {
                #pragma unroll
                for (int nb = 0; nb < 4; nb++) {
                    int rg = 32*wc2 + 8*nb + g;
                    int bo  = so + rg*PITCH + kb;
                    int so2 = so + (64 + rg)*PITCH + kb;
                    uint32_t b0 = *(const uint32_t*)(sm + O_BH + bo);
                    uint32_t b1 = *(const uint32_t*)(sm + O_BH + bo + 8);
                    uint32_t c0 = *(const uint32_t*)(sm + O_BL + bo);
                    uint32_t c1 = *(const uint32_t*)(sm + O_BL + bo + 8);
                    uint32_t d0 = *(const uint32_t*)(sm + O_BH + so2);
                    uint32_t d1 = *(const uint32_t*)(sm + O_BH + so2 + 8);
                    uint32_t e0 = *(const uint32_t*)(sm + O_BL + so2);
                    uint32_t e1 = *(const uint32_t*)(sm + O_BL + so2 + 8);
                    #pragma unroll
                    for (int rb = 0; rb < 2; rb++) {
                        MMA_BF16(accg[rb][nb], ah[rb][0], ah[rb][1], ah[rb][2], ah[rb][3], b0, b1);
                        MMA_BF16(accg[rb][nb], al[rb][0], al[rb][1], al[rb][2], al[rb][3], b0, b1);
                        MMA_BF16(accg[rb][nb], ah[rb][0], ah[rb][1], ah[rb][2], ah[rb][3], c0, c1);
                        MMA_BF16(accs[rb][nb], ah[rb][0], ah[rb][1], ah[rb][2], ah[rb][3], d0, d1);
                        MMA_BF16(accs[rb][nb], al[rb][0], al[rb][1], al[rb][2], al[rb][3], d0, d1);
                        MMA_BF16(accs[rb][nb], ah[rb][0], ah[rb][1], ah[rb][2], ah[rb][3], e0, e1);
                    }
                }
            }
        }
    }

    // ---- epilogue ----
    float cs0[STATS ? 8 : 1], cs1[STATS ? 8 : 1], cq0[STATS ? 8 : 1], cq1[STATS ? 8 : 1];
    if (STATS) {
        #pragma unroll
        for (int nb = 0; nb < 8; nb++) { cs0[nb]=0.f; cs1[nb]=0.f; cq0[nb]=0.f; cq1[nb]=0.f; }
    }
    #pragma unroll
    for (int rb = 0; rb < 2; rb++) {
        int m0 = bm + 32*wr + 16*rb + g;
        #pragma unroll
        for (int nb = 0; nb < (DUAL ? 4 : 8); nb++) {
            if (!DUAL) {
                int col = bn + 64*wc2 + 8*nb + 2*t;
                float2 v0 = make_float2(accg[rb][nb][0], accg[rb][nb][1]);
                float2 v1 = make_float2(accg[rb][nb][2], accg[rb][nb][3]);
                if (EPI == 0) {
                    if (bias != nullptr) {
                        float2 bv = *(const float2*)(bias + col);
                        v0.x += bv.x; v0.y += bv.y; v1.x += bv.x; v1.y += bv.y;
                    }
                } else if (EPI == 1) {
                    float2 aa = *(const float2*)(g_bna + col);
                    float2 ab = *(const float2*)(g_bnb + col);
                    float2 dv = *(const float2*)(dvec + col);
                    float2 h0 = *(const float2*)(aux + (size_t)m0*DE + col);
                    float2 h1 = *(const float2*)(aux + (size_t)(m0+8)*DE + col);
                    v0.x += fmaf(aa.x, h0.x, ab.x)*dv.x;
                    v0.y += fmaf(aa.y, h0.y, ab.y)*dv.y;
                    v1.x += fmaf(aa.x, h1.x, ab.x)*dv.x;
                    v1.y += fmaf(aa.y, h1.y, ab.y)*dv.y;
                } else if (EPI == 2) {
                    float2 bv = *(const float2*)(bias + col);
                    float2 y0 = *(const float2*)(aux + (size_t)m0*OUTW + col);
                    float2 y1 = *(const float2*)(aux + (size_t)(m0+8)*OUTW + col);
                    v0.x += bv.x + y0.x; v0.y += bv.y + y0.y;
                    v1.x += bv.x + y1.x; v1.y += bv.y + y1.y;
                }
                if (STATS) {
                    cs0[nb] += v0.x + v1.x;
                    cs1[nb] += v0.y + v1.y;
                    cq0[nb] += v0.x*v0.x + v1.x*v1.x;
                    cq1[nb] += v0.y*v0.y + v1.y*v1.y;
                }
                if (OUT16) {
                    __nv_bfloat16* C16 = (__nv_bfloat16*)C;
                    __nv_bfloat162 p0 = __floats2bfloat162_rn(v0.x, v0.y);
                    __nv_bfloat162 p1 = __floats2bfloat162_rn(v1.x, v1.y);
                    *(__nv_bfloat162*)(C16 + (size_t)m0*OUTW + col)     = p0;
                    *(__nv_bfloat162*)(C16 + (size_t)(m0+8)*OUTW + col) = p1;
                } else {
                    *(float2*)(C + (size_t)m0*OUTW + col)     = v0;
                    *(float2*)(C + (size_t)(m0+8)*OUTW + col) = v1;
                }
            } else {
                int jc = bn + 32*wc2 + 8*nb + 2*t;
                float2 bg = *(const float2*)(bias + jc);
                float2 bs = *(const float2*)(bias + 256 + jc);
                float g0 = accg[rb][nb][0] + bg.x, s0 = accs[rb][nb][0] + bs.x;
                float g1 = accg[rb][nb][1] + bg.y, s1 = accs[rb][nb][1] + bs.y;
                float g2 = accg[rb][nb][2] + bg.x, s2 = accs[rb][nb][2] + bs.x;
                float g3 = accg[rb][nb][3] + bg.y, s3 = accs[rb][nb][3] + bs.y;
                float2 v0, v1;
                v0.x = g0 * (1.f/(1.f + expf(-s0)));
                v0.y = g1 * (1.f/(1.f + expf(-s1)));
                v1.x = g2 * (1.f/(1.f + expf(-s2)));
                v1.y = g3 * (1.f/(1.f + expf(-s3)));
                *(float2*)(C + (size_t)m0*OUTW + jc)     = v0;
                *(float2*)(C + (size_t)(m0+8)*OUTW + jc) = v1;
            }
        }
    }

    if (STATS && !DUAL) {
        #pragma unroll
        for (int nb = 0; nb < 8; nb++) {
            #pragma unroll
            for (int m = 4; m <= 16; m <<= 1) {
                cs0[nb] += __shfl_xor_sync(0xffffffffu, cs0[nb], m);
                cs1[nb] += __shfl_xor_sync(0xffffffffu, cs1[nb], m);
                cq0[nb] += __shfl_xor_sync(0xffffffffu, cq0[nb], m);
                cq1[nb] += __shfl_xor_sync(0xffffffffu, cq1[nb], m);
            }
        }
        __syncthreads();
        float* spart = (float*)sm;
        if (lane < 4) {
            #pragma unroll
            for (int nb = 0; nb < 8; nb++) {
                int col = 64*wc2 + 8*nb + 2*lane;
                spart[wr*128 + col]       = cs0[nb];
                spart[wr*128 + col + 1]   = cs1[nb];
                spart[512 + wr*128 + col]     = cq0[nb];
                spart[512 + wr*128 + col + 1] = cq1[nb];
            }
        }
        __syncthreads();
        if (tid < 128) {
            float s  = spart[tid] + spart[128+tid] + spart[256+tid] + spart[384+tid];
            float s2 = spart[512+tid] + spart[640+tid] + spart[768+tid] + spart[896+tid];
            g_bnpart[blockIdx.y*(2*DE) + tid]      = s;
            g_bnpart[blockIdx.y*(2*DE) + DE + tid] = s2;
        }
    }
}

// ---------------- LRU scan ----------------
__device__ __forceinline__ float2 cstep(float2 lam, float2 s, float2 u) {
    float2 t;
    t.x = fmaf(lam.x, s.x, fmaf(-lam.y, s.y, u.x));
    t.y = fmaf(lam.x, s.y, fmaf( lam.y, s.x, u.y));
    return t;
}
__device__ __forceinline__ float2 bf2f(uint32_t raw) {
    __nv_bfloat162 u2 = *(__nv_bfloat162*)&raw;
    return make_float2(__bfloat162float(u2.x), __bfloat162float(u2.y));
}
__global__ void scanA_kernel(int blk) {
    int g  = blockIdx.x*256 + threadIdx.x;
    int h  = g & 255;
    int bc = g >> 8;
    int b  = bc >> 4;
    int c  = bc & 15;
    float2 lam = g_lam[blk*HH + h];
    float2 s = make_float2(0.f, 0.f);
    const uint32_t* bu = (const uint32_t*)g_bu16 + ((size_t)(b*TT + c*CLEN)*256 + h);
    #pragma unroll 8
    for (int i = 0; i < CLEN; i++) {
        float2 u = bf2f(bu[(size_t)i*256]);
        s = cstep(lam, s, u);
    }
    g_carry[bc*HH + h] = s;
}
__global__ void scanB_kernel(int blk) {
    int b = blockIdx.x;
    int h = threadIdx.x;
    float2 lam = g_lam[blk*HH + h];
    float2 lp = lam;
    #pragma unroll
    for (int i = 0; i < 8; i++) {
        float2 t;
        t.x = lp.x*lp.x - lp.y*lp.y;
        t.y = 2.f*lp.x*lp.y;
        lp = t;
    }
    float2 s = make_float2(0.f, 0.f);
    for (int c = 0; c < NCH; c++) {
        g_inc[(b*NCH + c)*HH + h] = s;
        float2 cr = g_carry[(b*NCH + c)*HH + h];
        s = cstep(lp, s, cr);
    }
}
__global__ void scanC_kernel(int blk) {
    int g  = blockIdx.x*256 + threadIdx.x;
    int h  = g & 255;
    int bc = g >> 8;
    int b  = bc >> 4;
    int c  = bc & 15;
    float2 lam = g_lam[blk*HH + h];
    float2 s = g_inc[bc*HH + h];
    const uint32_t* bu = (const uint32_t*)g_bu16 + ((size_t)(b*TT + c*CLEN)*256 + h);
    float2* st = g_state + ((size_t)(b*TT + c*CLEN)*HH + h);
    #pragma unroll 8
    for (int i = 0; i < CLEN; i++) {
        float2 u = bf2f(bu[(size_t)i*256]);
        s = cstep(lam, s, u);
        st[(size_t)i*HH] = s;
    }
}

// ---------------- final: mean-pool + head ----------------
__global__ void final_kernel(const float* __restrict__ h,
                             const float* __restrict__ Wout,
                             const float* __restrict__ bout,
                             float* __restrict__ out) {
    __shared__ float pooled[DE];
    int b = blockIdx.x;
    int f = threadIdx.x;
    float s = 0.f;
    const float* p = h + (size_t)b*TT*DE + f;
    #pragma unroll 4
    for (int t = 0; t < TT; t++) s += p[(size_t)t*DE];
    pooled[f] = s * (1.f/TT);
    __syncthreads();
    if (f < OD) {
        float acc = bout[f];
        #pragma unroll 4
        for (int d = 0; d < DE; d++) acc = fmaf(pooled[d], Wout[d*OD + f], acc);
        out[b*OD + f] = acc;
    }
}

// ---------------- launch ----------------
extern "C" void kernel_launch(void* const* d_in, const int* in_sizes, int n_in,
                              void* d_out, int out_size) {
    const float* x         = (const float*)d_in[0];
    const float* nu_log    = (const float*)d_in[1];
    const float* theta_log = (const float*)d_in[2];
    const float* B_re      = (const float*)d_in[3];
    const float* B_im      = (const float*)d_in[4];
    const float* C_re      = (const float*)d_in[5];
    const float* C_im      = (const float*)d_in[6];
    const float* D_lru     = (const float*)d_in[7];
    const float* W1        = (const float*)d_in[8];
    const float* b1        = (const float*)d_in[9];
    const float* W2        = (const float*)d_in[10];
    const float* b2        = (const float*)d_in[11];
    const float* bn_scale  = (const float*)d_in[12];
    const float* bn_bias   = (const float*)d_in[13];
    const float* W_enc     = (const float*)d_in[14];
    const float* b_enc     = (const float*)d_in[15];
    const float* W_out     = (const float*)d_in[16];
    const float* b_out     = (const float*)d_in[17];
    float* out = (float*)d_out;

    float *yenc, *h, *lru, *glu, *state;
    __nv_bfloat16 *bu16, *wbh, *wbl, *wch, *wcl, *w1h, *w1l, *w2h, *w2l, *weh, *wel;
    cudaGetSymbolAddress((void**)&yenc, g_yenc);
    cudaGetSymbolAddress((void**)&h,    g_h);
    cudaGetSymbolAddress((void**)&bu16, g_bu16);
    cudaGetSymbolAddress((void**)&state,g_state);
    cudaGetSymbolAddress((void**)&lru,  g_lru);
    cudaGetSymbolAddress((void**)&glu,  g_glu);
    cudaGetSymbolAddress((void**)&wbh,  g_WBh);
    cudaGetSymbolAddress((void**)&wbl,  g_WBl);
    cudaGetSymbolAddress((void**)&wch,  g_WCh);
    cudaGetSymbolAddress((void**)&wcl,  g_WCl);
    cudaGetSymbolAddress((void**)&w1h,  g_W1h);
    cudaGetSymbolAddress((void**)&w1l,  g_W1l);
    cudaGetSymbolAddress((void**)&w2h,  g_W2h);
    cudaGetSymbolAddress((void**)&w2l,  g_W2l);
    cudaGetSymbolAddress((void**)&weh,  g_WEh);
    cudaGetSymbolAddress((void**)&wel,  g_WEl);

    cudaFuncSetAttribute(gemm_mma<64, 128, 0, 0, 0, 0, 1>,  cudaFuncAttributeMaxDynamicSharedMemorySize, SMEM_BYTES);
    cudaFuncSetAttribute(gemm_mma<128, 512, 1, 0, 0, 1, 0>, cudaFuncAttributeMaxDynamicSharedMemorySize, SMEM_BYTES);
    cudaFuncSetAttribute(gemm_mma<512, 128, 0, 1, 0, 0, 0>, cudaFuncAttributeMaxDynamicSharedMemorySize, SMEM_BYTES);
    cudaFuncSetAttribute(gemm_mma<128, 256, 0, 0, 1, 0, 0>, cudaFuncAttributeMaxDynamicSharedMemorySize, SMEM_BYTES);
    cudaFuncSetAttribute(gemm_mma<256, 128, 0, 2, 0, 0, 1>, cudaFuncAttributeMaxDynamicSharedMemorySize, SMEM_BYTES);

    prep_lam_kernel<<<NBLKS, HH>>>(nu_log, theta_log);
    prep_WE_kernel<<<(DE*TSD + 255)/256, 256>>>(W_enc);
    prep_WB_kernel<<<(NBLKS*512*DE + 255)/256, 256>>>(B_re, B_im);

    // encoder: y_enc = x @ W_enc + b_enc  (+ BN partials for block 0)
    gemm_mma<64, 128, 0, 0, 0, 0, 1><<<dim3(1, NR/128), 256, SMEM_BYTES>>>(
        x, weh, wel, yenc, b_enc, nullptr, nullptr);

    prep_WC_kernel<<<(NBLKS*DE*512 + 255)/256, 256>>>(C_re, C_im);
    prep_W1_kernel<<<(NBLKS*512*DE + 255)/256, 256>>>(W1);
    prep_W2_kernel<<<(NBLKS*DE*256 + 255)/256, 256>>>(W2);

    const float* hp = yenc;
    for (int blk = 0; blk < NBLKS; blk++) {
        bn_stats2_kernel<<<1, 128>>>(bn_scale + blk*DE, bn_bias + blk*DE);

        // Bu = BN(h) @ WB  (bf16 out)
        gemm_mma<128, 512, 1, 0, 0, 1, 0><<<dim3(4, NR/128), 256, SMEM_BYTES>>>(
            hp, wbh + (size_t)blk*512*128, wbl + (size_t)blk*512*128,
            (float*)bu16, nullptr, nullptr, nullptr);

        scanA_kernel<<<NR/256, 256>>>(blk);
        scanB_kernel<<<BB, HH>>>(blk);
        scanC_kernel<<<NR/256, 256>>>(blk);

        // lru = Re(state @ C) + BN(h) * D   (fp32 state, 3-term)
        gemm_mma<512, 128, 0, 1, 0, 0, 0><<<dim3(1, NR/128), 256, SMEM_BYTES>>>(
            state, wch + (size_t)blk*128*512, wcl + (size_t)blk*128*512,
            lru, nullptr, hp, D_lru + blk*DE);

        // glu = GLU(lru @ W1 + b1)
        gemm_mma<128, 256, 0, 0, 1, 0, 0><<<dim3(4, NR/128), 256, SMEM_BYTES>>>(
            lru, w1h + (size_t)blk*512*128, w1l + (size_t)blk*512*128,
            glu, b1 + (size_t)blk*LDF, nullptr, nullptr);

        // h = glu @ W2 + b2 + y_enc  (+ BN partials for next block)
        gemm_mma<256, 128, 0, 2, 0, 0, 1><<<dim3(1, NR/128), 256, SMEM_BYTES>>>(
            glu, w2h + (size_t)blk*128*256, w2l + (size_t)blk*128*256,
            h, b2 + blk*DE, yenc, nullptr);

        hp = h;
    }

    final_kernel<<<BB, DE>>>(hp, W_out, b_out, out);
}